// round 6
// baseline (speedup 1.0000x reference)
#include <cuda_runtime.h>
#include <math.h>

#define N_NODES 50000
#define N_EDGES 1600000
#define DIM     128
#define NHEADS  4
#define NEG_SLOPE 0.2f

// ---------------- scratch (static device arrays; no allocation) ----------------
__device__ int   g_deg   [N_NODES];
__device__ int   g_rowptr[N_NODES + 1];
__device__ int   g_cursor[N_NODES];
__device__ int   g_cols  [N_EDGES];
__device__ float g_hq    [N_NODES * NHEADS];
__device__ float g_kact  [N_NODES * NHEADS];
__device__ float g_qagg  [N_NODES * NHEADS];
__device__ float g_sc    [(size_t)N_EDGES * NHEADS];  // scores, then exp(s - max)
__device__ float g_alpha [N_EDGES];
__device__ float g_hproj [(size_t)N_NODES * DIM];

// ---------------- helpers ----------------
static __device__ __forceinline__ float leaky_f(float v) {
    return v >= 0.f ? v : NEG_SLOPE * v;
}
static __device__ __forceinline__ unsigned long long pack2(float lo, float hi) {
    unsigned long long r;
    asm("mov.b64 %0, {%1,%2};" : "=l"(r) : "f"(lo), "f"(hi));
    return r;
}
static __device__ __forceinline__ void unpack2(unsigned long long v, float& lo, float& hi) {
    asm("mov.b64 {%0,%1}, %2;" : "=f"(lo), "=f"(hi) : "l"(v));
}

// ---------------- CSR build ----------------

__global__ void k_zero_deg() {
    int i = blockIdx.x * blockDim.x + threadIdx.x;
    if (i < N_NODES) g_deg[i] = 0;
}

__global__ void k_hist(const int* __restrict__ ei) {
    int e = blockIdx.x * blockDim.x + threadIdx.x;
    if (e >= N_EDGES) return;
    atomicAdd(&g_deg[ei[e]], 1);   // no return use -> RED
}

// single-block exclusive scan of g_deg -> g_rowptr / g_cursor
__global__ __launch_bounds__(1024) void k_scan() {
    __shared__ int sh[1024];
    const int T = 1024;
    const int per = (N_NODES + T - 1) / T;   // 49
    int t = threadIdx.x;
    int base = t * per;
    int s = 0;
    for (int i = 0; i < per; i++) {
        int idx = base + i;
        if (idx < N_NODES) s += g_deg[idx];
    }
    sh[t] = s;
    __syncthreads();
    for (int off = 1; off < T; off <<= 1) {
        int v = (t >= off) ? sh[t - off] : 0;
        __syncthreads();
        sh[t] += v;
        __syncthreads();
    }
    int run = (t == 0) ? 0 : sh[t - 1];
    for (int i = 0; i < per; i++) {
        int idx = base + i;
        if (idx < N_NODES) {
            g_rowptr[idx] = run;
            g_cursor[idx] = run;
            run += g_deg[idx];
        }
    }
    if (t == T - 1) g_rowptr[N_NODES] = run;
}

__global__ void k_scatter(const int* __restrict__ ei) {
    int e = blockIdx.x * blockDim.x + threadIdx.x;
    if (e >= N_EDGES) return;
    int row = ei[e];
    int col = ei[N_EDGES + e];
    int pos = atomicAdd(&g_cursor[row], 1);
    g_cols[pos] = col;
}

// ---------------- projections ----------------

// per-node h_q = x@Wq^T, k_act = leaky(x@Wk^T). One warp per node.
__global__ void k_qk(const float* __restrict__ x,
                     const float* __restrict__ Wq,
                     const float* __restrict__ Wk) {
    int warp = (blockIdx.x * blockDim.x + threadIdx.x) >> 5;
    if (warp >= N_NODES) return;
    int lane = threadIdx.x & 31;

    float4 xv = *(const float4*)&x[(size_t)warp * DIM + lane * 4];
    float q[NHEADS], k[NHEADS];
#pragma unroll
    for (int h = 0; h < NHEADS; h++) {
        float4 wq = *(const float4*)&Wq[h * DIM + lane * 4];
        float4 wk = *(const float4*)&Wk[h * DIM + lane * 4];
        q[h] = xv.x * wq.x + xv.y * wq.y + xv.z * wq.z + xv.w * wq.w;
        k[h] = xv.x * wk.x + xv.y * wk.y + xv.z * wk.z + xv.w * wk.w;
    }
#pragma unroll
    for (int off = 16; off > 0; off >>= 1) {
#pragma unroll
        for (int h = 0; h < NHEADS; h++) {
            q[h] += __shfl_xor_sync(0xffffffffu, q[h], off);
            k[h] += __shfl_xor_sync(0xffffffffu, k[h], off);
        }
    }
    if (lane == 0) {
#pragma unroll
        for (int h = 0; h < NHEADS; h++) {
            g_hq[warp * NHEADS + h]   = q[h];
            g_kact[warp * NHEADS + h] = leaky_f(k[h]);
        }
    }
}

// h_proj = x @ Wl^T + bl : 128x128 tile per block, packed f32x2 FMA.
__global__ __launch_bounds__(256) void k_gemm(const float* __restrict__ x,
                                              const float* __restrict__ Wl,
                                              const float* __restrict__ bl) {
    __shared__ float xs[32][DIM];
    __shared__ float ws[32][DIM];

    const int tid = threadIdx.x;
    const int tm = tid >> 4;
    const int tn = tid & 15;
    const int m0 = blockIdx.x * 128;

    unsigned long long acc[8][4];
#pragma unroll
    for (int i = 0; i < 8; i++)
#pragma unroll
        for (int j = 0; j < 4; j++) acc[i][j] = 0ull;

    const int lrow = tid >> 1;
    const int lk   = (tid & 1) * 16;

    for (int k0 = 0; k0 < DIM; k0 += 32) {
        __syncthreads();
        {
            int gm = m0 + lrow;
#pragma unroll
            for (int q = 0; q < 16; q += 4) {
                float4 v = make_float4(0.f, 0.f, 0.f, 0.f);
                if (gm < N_NODES)
                    v = *(const float4*)&x[(size_t)gm * DIM + k0 + lk + q];
                xs[lk + q + 0][lrow] = v.x;
                xs[lk + q + 1][lrow] = v.y;
                xs[lk + q + 2][lrow] = v.z;
                xs[lk + q + 3][lrow] = v.w;
            }
        }
        {
#pragma unroll
            for (int q = 0; q < 16; q += 4) {
                float4 w = *(const float4*)&Wl[(size_t)lrow * DIM + k0 + lk + q];
                ws[lk + q + 0][lrow] = w.x;
                ws[lk + q + 1][lrow] = w.y;
                ws[lk + q + 2][lrow] = w.z;
                ws[lk + q + 3][lrow] = w.w;
            }
        }
        __syncthreads();

#pragma unroll 8
        for (int kk = 0; kk < 32; kk++) {
            float4 a0 = *(const float4*)&xs[kk][tm * 8];
            float4 a1 = *(const float4*)&xs[kk][tm * 8 + 4];
            unsigned long long a2[8];
            a2[0] = pack2(a0.x, a0.x); a2[1] = pack2(a0.y, a0.y);
            a2[2] = pack2(a0.z, a0.z); a2[3] = pack2(a0.w, a0.w);
            a2[4] = pack2(a1.x, a1.x); a2[5] = pack2(a1.y, a1.y);
            a2[6] = pack2(a1.z, a1.z); a2[7] = pack2(a1.w, a1.w);
            unsigned long long b2[4];
#pragma unroll
            for (int j = 0; j < 4; j++) {
                float2 b = *(const float2*)&ws[kk][tn * 2 + 32 * j];
                b2[j] = pack2(b.x, b.y);
            }
#pragma unroll
            for (int i = 0; i < 8; i++)
#pragma unroll
                for (int j = 0; j < 4; j++)
                    asm volatile("fma.rn.f32x2 %0, %1, %2, %0;"
                                 : "+l"(acc[i][j]) : "l"(a2[i]), "l"(b2[j]));
        }
    }

#pragma unroll
    for (int j = 0; j < 4; j++) {
        int o = tn * 2 + 32 * j;
        float2 blv = *(const float2*)&bl[o];
#pragma unroll
        for (int i = 0; i < 8; i++) {
            int m = m0 + tm * 8 + i;
            if (m < N_NODES) {
                float lo, hi;
                unpack2(acc[i][j], lo, hi);
                *(float2*)&g_hproj[(size_t)m * DIM + o] =
                    make_float2(lo + blv.x, hi + blv.y);
            }
        }
    }
}

// ---------------- CSR edge phase (no atomics) ----------------

// q_agg[i] = sum over nbrs of h_q[col]; warp per node
__global__ void k_qagg_csr() {
    int node = (blockIdx.x * blockDim.x + threadIdx.x) >> 5;
    if (node >= N_NODES) return;
    int lane = threadIdx.x & 31;
    int rp0 = g_rowptr[node], rp1 = g_rowptr[node + 1];
    float4 acc = make_float4(0.f, 0.f, 0.f, 0.f);
    for (int j = rp0 + lane; j < rp1; j += 32) {
        int c = g_cols[j];
        float4 h = ((const float4*)g_hq)[c];
        acc.x += h.x; acc.y += h.y; acc.z += h.z; acc.w += h.w;
    }
#pragma unroll
    for (int off = 16; off > 0; off >>= 1) {
        acc.x += __shfl_xor_sync(0xffffffffu, acc.x, off);
        acc.y += __shfl_xor_sync(0xffffffffu, acc.y, off);
        acc.z += __shfl_xor_sync(0xffffffffu, acc.z, off);
        acc.w += __shfl_xor_sync(0xffffffffu, acc.w, off);
    }
    if (lane == 0) ((float4*)g_qagg)[node] = acc;
}

// full per-node segment softmax -> alpha_mean; warp per node
__global__ void k_soft() {
    int node = (blockIdx.x * blockDim.x + threadIdx.x) >> 5;
    if (node >= N_NODES) return;
    int lane = threadIdx.x & 31;
    int rp0 = g_rowptr[node], rp1 = g_rowptr[node + 1];
    float4 kact = ((const float4*)g_kact)[node];

    // pass 1: scores + max
    float4 m = make_float4(-INFINITY, -INFINITY, -INFINITY, -INFINITY);
    for (int j = rp0 + lane; j < rp1; j += 32) {
        int c = g_cols[j];
        float4 q = ((const float4*)g_qagg)[c];
        float4 s = make_float4(kact.x * q.x, kact.y * q.y, kact.z * q.z, kact.w * q.w);
        ((float4*)g_sc)[j] = s;
        m.x = fmaxf(m.x, s.x); m.y = fmaxf(m.y, s.y);
        m.z = fmaxf(m.z, s.z); m.w = fmaxf(m.w, s.w);
    }
#pragma unroll
    for (int off = 16; off > 0; off >>= 1) {
        m.x = fmaxf(m.x, __shfl_xor_sync(0xffffffffu, m.x, off));
        m.y = fmaxf(m.y, __shfl_xor_sync(0xffffffffu, m.y, off));
        m.z = fmaxf(m.z, __shfl_xor_sync(0xffffffffu, m.z, off));
        m.w = fmaxf(m.w, __shfl_xor_sync(0xffffffffu, m.w, off));
    }

    // pass 2: exp + sum (store exp in place)
    float4 sum = make_float4(0.f, 0.f, 0.f, 0.f);
    for (int j = rp0 + lane; j < rp1; j += 32) {
        float4 s = ((const float4*)g_sc)[j];
        float4 ex = make_float4(__expf(s.x - m.x), __expf(s.y - m.y),
                                __expf(s.z - m.z), __expf(s.w - m.w));
        ((float4*)g_sc)[j] = ex;
        sum.x += ex.x; sum.y += ex.y; sum.z += ex.z; sum.w += ex.w;
    }
#pragma unroll
    for (int off = 16; off > 0; off >>= 1) {
        sum.x += __shfl_xor_sync(0xffffffffu, sum.x, off);
        sum.y += __shfl_xor_sync(0xffffffffu, sum.y, off);
        sum.z += __shfl_xor_sync(0xffffffffu, sum.z, off);
        sum.w += __shfl_xor_sync(0xffffffffu, sum.w, off);
    }
    float4 inv = make_float4(1.f / (sum.x + 1e-8f), 1.f / (sum.y + 1e-8f),
                             1.f / (sum.z + 1e-8f), 1.f / (sum.w + 1e-8f));

    // pass 3: alpha_mean
    for (int j = rp0 + lane; j < rp1; j += 32) {
        float4 ex = ((const float4*)g_sc)[j];
        g_alpha[j] = 0.25f * (ex.x * inv.x + ex.y * inv.y + ex.z * inv.z + ex.w * inv.w);
    }
}

// out[i] = leaky( sum_j alpha_j * h_proj[col_j] ); warp per node, plain stores
__global__ __launch_bounds__(256) void k_agg_csr(float* __restrict__ out) {
    int node = (blockIdx.x * blockDim.x + threadIdx.x) >> 5;
    if (node >= N_NODES) return;
    int lane = threadIdx.x & 31;
    int rp0 = g_rowptr[node], rp1 = g_rowptr[node + 1];

    float4 acc = make_float4(0.f, 0.f, 0.f, 0.f);
    int j = rp0;
    for (; j + 4 <= rp1; j += 4) {
#pragma unroll
        for (int u = 0; u < 4; u++) {
            float a = __ldg(&g_alpha[j + u]);
            int   c = __ldg(&g_cols[j + u]);
            float4 v = *(const float4*)&g_hproj[(size_t)c * DIM + lane * 4];
            acc.x += a * v.x; acc.y += a * v.y; acc.z += a * v.z; acc.w += a * v.w;
        }
    }
    for (; j < rp1; j++) {
        float a = __ldg(&g_alpha[j]);
        int   c = __ldg(&g_cols[j]);
        float4 v = *(const float4*)&g_hproj[(size_t)c * DIM + lane * 4];
        acc.x += a * v.x; acc.y += a * v.y; acc.z += a * v.z; acc.w += a * v.w;
    }
    acc.x = leaky_f(acc.x); acc.y = leaky_f(acc.y);
    acc.z = leaky_f(acc.z); acc.w = leaky_f(acc.w);
    *(float4*)&out[(size_t)node * DIM + lane * 4] = acc;
}

// ---------------- launch ----------------
extern "C" void kernel_launch(void* const* d_in, const int* in_sizes, int n_in,
                              void* d_out, int out_size) {
    const float* x  = (const float*)d_in[0];
    const int*   ei = (const int*)d_in[1];
    const float* Wq = (const float*)d_in[2];
    const float* Wk = (const float*)d_in[3];
    const float* Wl = (const float*)d_in[4];
    const float* bl = (const float*)d_in[5];
    float* out = (float*)d_out;

    const int TB = 256;
    const int EDGE_BLOCKS = (N_EDGES + TB - 1) / TB;
    const int NODE_WARP_BLOCKS = (N_NODES * 32 + TB - 1) / TB;   // 6250

    k_zero_deg<<<(N_NODES + TB - 1) / TB, TB>>>();
    k_hist<<<EDGE_BLOCKS, TB>>>(ei);
    k_scan<<<1, 1024>>>();
    k_scatter<<<EDGE_BLOCKS, TB>>>(ei);
    k_qk<<<NODE_WARP_BLOCKS, TB>>>(x, Wq, Wk);
    k_gemm<<<(N_NODES + 127) / 128, TB>>>(x, Wl, bl);
    k_qagg_csr<<<NODE_WARP_BLOCKS, TB>>>();
    k_soft<<<NODE_WARP_BLOCKS, TB>>>();
    k_agg_csr<<<NODE_WARP_BLOCKS, TB>>>(out);
}

// round 9
// speedup vs baseline: 1.5449x; 1.5449x over previous
#include <cuda_runtime.h>
#include <math.h>

#define N_NODES 50000
#define N_EDGES 1600000
#define DIM     128
#define NHEADS  4
#define NEG_SLOPE 0.2f
#define CAP     128   // smem fast-path neighbor cap (Poisson(32) max deg ~70)

// ---------------- scratch (static device arrays; no allocation) ----------------
__device__ int   g_deg   [N_NODES];
__device__ int   g_rowptr[N_NODES + 1];
__device__ int   g_cursor[N_NODES];
__device__ int   g_cols  [N_EDGES];
__device__ float g_hq    [N_NODES * NHEADS];
__device__ float g_kact  [N_NODES * NHEADS];
__device__ float g_qagg  [N_NODES * NHEADS];
__device__ float g_hproj [(size_t)N_NODES * DIM];

// ---------------- helpers ----------------
static __device__ __forceinline__ float leaky_f(float v) {
    return v >= 0.f ? v : NEG_SLOPE * v;
}
static __device__ __forceinline__ unsigned long long pack2(float lo, float hi) {
    unsigned long long r;
    asm("mov.b64 %0, {%1,%2};" : "=l"(r) : "f"(lo), "f"(hi));
    return r;
}
static __device__ __forceinline__ void unpack2(unsigned long long v, float& lo, float& hi) {
    asm("mov.b64 {%0,%1}, %2;" : "=f"(lo), "=f"(hi) : "l"(v));
}

// ---------------- CSR build ----------------

__global__ void k_zero_deg() {
    int i = blockIdx.x * blockDim.x + threadIdx.x;
    if (i < N_NODES) g_deg[i] = 0;
}

__global__ void k_hist(const int* __restrict__ ei) {
    int e = blockIdx.x * blockDim.x + threadIdx.x;
    if (e >= N_EDGES) return;
    atomicAdd(&g_deg[ei[e]], 1);
}

__global__ __launch_bounds__(1024) void k_scan() {
    __shared__ int sh[1024];
    const int T = 1024;
    const int per = (N_NODES + T - 1) / T;
    int t = threadIdx.x;
    int base = t * per;
    int s = 0;
    for (int i = 0; i < per; i++) {
        int idx = base + i;
        if (idx < N_NODES) s += g_deg[idx];
    }
    sh[t] = s;
    __syncthreads();
    for (int off = 1; off < T; off <<= 1) {
        int v = (t >= off) ? sh[t - off] : 0;
        __syncthreads();
        sh[t] += v;
        __syncthreads();
    }
    int run = (t == 0) ? 0 : sh[t - 1];
    for (int i = 0; i < per; i++) {
        int idx = base + i;
        if (idx < N_NODES) {
            g_rowptr[idx] = run;
            g_cursor[idx] = run;
            run += g_deg[idx];
        }
    }
    if (t == T - 1) g_rowptr[N_NODES] = run;
}

__global__ void k_scatter(const int* __restrict__ ei) {
    int e = blockIdx.x * blockDim.x + threadIdx.x;
    if (e >= N_EDGES) return;
    int row = ei[e];
    int col = ei[N_EDGES + e];
    int pos = atomicAdd(&g_cursor[row], 1);
    g_cols[pos] = col;
}

// ---------------- projections ----------------

__global__ void k_qk(const float* __restrict__ x,
                     const float* __restrict__ Wq,
                     const float* __restrict__ Wk) {
    int warp = (blockIdx.x * blockDim.x + threadIdx.x) >> 5;
    if (warp >= N_NODES) return;
    int lane = threadIdx.x & 31;

    float4 xv = *(const float4*)&x[(size_t)warp * DIM + lane * 4];
    float q[NHEADS], k[NHEADS];
#pragma unroll
    for (int h = 0; h < NHEADS; h++) {
        float4 wq = *(const float4*)&Wq[h * DIM + lane * 4];
        float4 wk = *(const float4*)&Wk[h * DIM + lane * 4];
        q[h] = xv.x * wq.x + xv.y * wq.y + xv.z * wq.z + xv.w * wq.w;
        k[h] = xv.x * wk.x + xv.y * wk.y + xv.z * wk.z + xv.w * wk.w;
    }
#pragma unroll
    for (int off = 16; off > 0; off >>= 1) {
#pragma unroll
        for (int h = 0; h < NHEADS; h++) {
            q[h] += __shfl_xor_sync(0xffffffffu, q[h], off);
            k[h] += __shfl_xor_sync(0xffffffffu, k[h], off);
        }
    }
    if (lane == 0) {
#pragma unroll
        for (int h = 0; h < NHEADS; h++) {
            g_hq[warp * NHEADS + h]   = q[h];
            g_kact[warp * NHEADS + h] = leaky_f(k[h]);
        }
    }
}

__global__ __launch_bounds__(256) void k_gemm(const float* __restrict__ x,
                                              const float* __restrict__ Wl,
                                              const float* __restrict__ bl) {
    __shared__ float xs[32][DIM];
    __shared__ float ws[32][DIM];

    const int tid = threadIdx.x;
    const int tm = tid >> 4;
    const int tn = tid & 15;
    const int m0 = blockIdx.x * 128;

    unsigned long long acc[8][4];
#pragma unroll
    for (int i = 0; i < 8; i++)
#pragma unroll
        for (int j = 0; j < 4; j++) acc[i][j] = 0ull;

    const int lrow = tid >> 1;
    const int lk   = (tid & 1) * 16;

    for (int k0 = 0; k0 < DIM; k0 += 32) {
        __syncthreads();
        {
            int gm = m0 + lrow;
#pragma unroll
            for (int q = 0; q < 16; q += 4) {
                float4 v = make_float4(0.f, 0.f, 0.f, 0.f);
                if (gm < N_NODES)
                    v = *(const float4*)&x[(size_t)gm * DIM + k0 + lk + q];
                xs[lk + q + 0][lrow] = v.x;
                xs[lk + q + 1][lrow] = v.y;
                xs[lk + q + 2][lrow] = v.z;
                xs[lk + q + 3][lrow] = v.w;
            }
        }
        {
#pragma unroll
            for (int q = 0; q < 16; q += 4) {
                float4 w = *(const float4*)&Wl[(size_t)lrow * DIM + k0 + lk + q];
                ws[lk + q + 0][lrow] = w.x;
                ws[lk + q + 1][lrow] = w.y;
                ws[lk + q + 2][lrow] = w.z;
                ws[lk + q + 3][lrow] = w.w;
            }
        }
        __syncthreads();

#pragma unroll 8
        for (int kk = 0; kk < 32; kk++) {
            float4 a0 = *(const float4*)&xs[kk][tm * 8];
            float4 a1 = *(const float4*)&xs[kk][tm * 8 + 4];
            unsigned long long a2[8];
            a2[0] = pack2(a0.x, a0.x); a2[1] = pack2(a0.y, a0.y);
            a2[2] = pack2(a0.z, a0.z); a2[3] = pack2(a0.w, a0.w);
            a2[4] = pack2(a1.x, a1.x); a2[5] = pack2(a1.y, a1.y);
            a2[6] = pack2(a1.z, a1.z); a2[7] = pack2(a1.w, a1.w);
            unsigned long long b2[4];
#pragma unroll
            for (int j = 0; j < 4; j++) {
                float2 b = *(const float2*)&ws[kk][tn * 2 + 32 * j];
                b2[j] = pack2(b.x, b.y);
            }
#pragma unroll
            for (int i = 0; i < 8; i++)
#pragma unroll
                for (int j = 0; j < 4; j++)
                    asm volatile("fma.rn.f32x2 %0, %1, %2, %0;"
                                 : "+l"(acc[i][j]) : "l"(a2[i]), "l"(b2[j]));
        }
    }

#pragma unroll
    for (int j = 0; j < 4; j++) {
        int o = tn * 2 + 32 * j;
        float2 blv = *(const float2*)&bl[o];
#pragma unroll
        for (int i = 0; i < 8; i++) {
            int m = m0 + tm * 8 + i;
            if (m < N_NODES) {
                float lo, hi;
                unpack2(acc[i][j], lo, hi);
                *(float2*)&g_hproj[(size_t)m * DIM + o] =
                    make_float2(lo + blv.x, hi + blv.y);
            }
        }
    }
}

// ---------------- q_agg (warp per node) ----------------
__global__ void k_qagg_csr() {
    int node = (blockIdx.x * blockDim.x + threadIdx.x) >> 5;
    if (node >= N_NODES) return;
    int lane = threadIdx.x & 31;
    int rp0 = g_rowptr[node], rp1 = g_rowptr[node + 1];
    float4 acc = make_float4(0.f, 0.f, 0.f, 0.f);
    for (int j = rp0 + lane; j < rp1; j += 32) {
        int c = g_cols[j];
        float4 h = ((const float4*)g_hq)[c];
        acc.x += h.x; acc.y += h.y; acc.z += h.z; acc.w += h.w;
    }
#pragma unroll
    for (int off = 16; off > 0; off >>= 1) {
        acc.x += __shfl_xor_sync(0xffffffffu, acc.x, off);
        acc.y += __shfl_xor_sync(0xffffffffu, acc.y, off);
        acc.z += __shfl_xor_sync(0xffffffffu, acc.z, off);
        acc.w += __shfl_xor_sync(0xffffffffu, acc.w, off);
    }
    if (lane == 0) ((float4*)g_qagg)[node] = acc;
}

// ---------------- fused softmax + aggregation (warp per node) ----------------
__global__ __launch_bounds__(256) void k_fused(float* __restrict__ out) {
    __shared__ float4 sex[8][CAP];   // per-warp per-edge exp values (4 heads)
    __shared__ float  sal[8][CAP];   // per-warp per-edge alpha_mean

    const int w    = threadIdx.x >> 5;
    const int lane = threadIdx.x & 31;
    const int node = (blockIdx.x * blockDim.x + threadIdx.x) >> 5;
    if (node >= N_NODES) return;

    const int rp0 = g_rowptr[node], rp1 = g_rowptr[node + 1];
    const int deg = rp1 - rp0;

    float4 acc = make_float4(0.f, 0.f, 0.f, 0.f);

    if (deg > 0 && deg <= CAP) {
        const float4 kact = ((const float4*)g_kact)[node];

        // pass 1: scores -> smem, running max
        float4 m = make_float4(-INFINITY, -INFINITY, -INFINITY, -INFINITY);
        for (int jj = lane; jj < deg; jj += 32) {
            int c = __ldg(&g_cols[rp0 + jj]);
            float4 q = ((const float4*)g_qagg)[c];
            float4 s = make_float4(kact.x * q.x, kact.y * q.y,
                                   kact.z * q.z, kact.w * q.w);
            sex[w][jj] = s;
            m.x = fmaxf(m.x, s.x); m.y = fmaxf(m.y, s.y);
            m.z = fmaxf(m.z, s.z); m.w = fmaxf(m.w, s.w);
        }
#pragma unroll
        for (int off = 16; off > 0; off >>= 1) {
            m.x = fmaxf(m.x, __shfl_xor_sync(0xffffffffu, m.x, off));
            m.y = fmaxf(m.y, __shfl_xor_sync(0xffffffffu, m.y, off));
            m.z = fmaxf(m.z, __shfl_xor_sync(0xffffffffu, m.z, off));
            m.w = fmaxf(m.w, __shfl_xor_sync(0xffffffffu, m.w, off));
        }

        // pass 2: exp in smem, running sum
        float4 sum = make_float4(0.f, 0.f, 0.f, 0.f);
        for (int jj = lane; jj < deg; jj += 32) {
            float4 s = sex[w][jj];
            float4 ex = make_float4(__expf(s.x - m.x), __expf(s.y - m.y),
                                    __expf(s.z - m.z), __expf(s.w - m.w));
            sex[w][jj] = ex;
            sum.x += ex.x; sum.y += ex.y; sum.z += ex.z; sum.w += ex.w;
        }
#pragma unroll
        for (int off = 16; off > 0; off >>= 1) {
            sum.x += __shfl_xor_sync(0xffffffffu, sum.x, off);
            sum.y += __shfl_xor_sync(0xffffffffu, sum.y, off);
            sum.z += __shfl_xor_sync(0xffffffffu, sum.z, off);
            sum.w += __shfl_xor_sync(0xffffffffu, sum.w, off);
        }
        float4 inv = make_float4(0.25f / (sum.x + 1e-8f), 0.25f / (sum.y + 1e-8f),
                                 0.25f / (sum.z + 1e-8f), 0.25f / (sum.w + 1e-8f));

        // pass 2.5: alpha_mean -> smem
        for (int jj = lane; jj < deg; jj += 32) {
            float4 ex = sex[w][jj];
            sal[w][jj] = ex.x * inv.x + ex.y * inv.y + ex.z * inv.z + ex.w * inv.w;
        }
        __syncwarp();

        // pass 3: aggregate h_proj, unrolled x4 for MLP
        int jj = 0;
        for (; jj + 4 <= deg; jj += 4) {
            float a0 = sal[w][jj + 0], a1 = sal[w][jj + 1];
            float a2 = sal[w][jj + 2], a3 = sal[w][jj + 3];
            int c0 = __ldg(&g_cols[rp0 + jj + 0]);
            int c1 = __ldg(&g_cols[rp0 + jj + 1]);
            int c2 = __ldg(&g_cols[rp0 + jj + 2]);
            int c3 = __ldg(&g_cols[rp0 + jj + 3]);
            float4 v0 = *(const float4*)&g_hproj[(size_t)c0 * DIM + lane * 4];
            float4 v1 = *(const float4*)&g_hproj[(size_t)c1 * DIM + lane * 4];
            float4 v2 = *(const float4*)&g_hproj[(size_t)c2 * DIM + lane * 4];
            float4 v3 = *(const float4*)&g_hproj[(size_t)c3 * DIM + lane * 4];
            acc.x += a0 * v0.x + a1 * v1.x + a2 * v2.x + a3 * v3.x;
            acc.y += a0 * v0.y + a1 * v1.y + a2 * v2.y + a3 * v3.y;
            acc.z += a0 * v0.z + a1 * v1.z + a2 * v2.z + a3 * v3.z;
            acc.w += a0 * v0.w + a1 * v1.w + a2 * v2.w + a3 * v3.w;
        }
        for (; jj < deg; jj++) {
            float a = sal[w][jj];
            int   c = __ldg(&g_cols[rp0 + jj]);
            float4 v = *(const float4*)&g_hproj[(size_t)c * DIM + lane * 4];
            acc.x += a * v.x; acc.y += a * v.y; acc.z += a * v.z; acc.w += a * v.w;
        }
    } else if (deg > CAP) {
        // fallback (correct for any degree; effectively never taken for this graph)
        const float4 kact = ((const float4*)g_kact)[node];
        float4 m = make_float4(-INFINITY, -INFINITY, -INFINITY, -INFINITY);
        for (int j = rp0 + lane; j < rp1; j += 32) {
            int c = g_cols[j];
            float4 q = ((const float4*)g_qagg)[c];
            m.x = fmaxf(m.x, kact.x * q.x); m.y = fmaxf(m.y, kact.y * q.y);
            m.z = fmaxf(m.z, kact.z * q.z); m.w = fmaxf(m.w, kact.w * q.w);
        }
#pragma unroll
        for (int off = 16; off > 0; off >>= 1) {
            m.x = fmaxf(m.x, __shfl_xor_sync(0xffffffffu, m.x, off));
            m.y = fmaxf(m.y, __shfl_xor_sync(0xffffffffu, m.y, off));
            m.z = fmaxf(m.z, __shfl_xor_sync(0xffffffffu, m.z, off));
            m.w = fmaxf(m.w, __shfl_xor_sync(0xffffffffu, m.w, off));
        }
        float4 sum = make_float4(0.f, 0.f, 0.f, 0.f);
        for (int j = rp0 + lane; j < rp1; j += 32) {
            int c = g_cols[j];
            float4 q = ((const float4*)g_qagg)[c];
            sum.x += __expf(kact.x * q.x - m.x);
            sum.y += __expf(kact.y * q.y - m.y);
            sum.z += __expf(kact.z * q.z - m.z);
            sum.w += __expf(kact.w * q.w - m.w);
        }
#pragma unroll
        for (int off = 16; off > 0; off >>= 1) {
            sum.x += __shfl_xor_sync(0xffffffffu, sum.x, off);
            sum.y += __shfl_xor_sync(0xffffffffu, sum.y, off);
            sum.z += __shfl_xor_sync(0xffffffffu, sum.z, off);
            sum.w += __shfl_xor_sync(0xffffffffu, sum.w, off);
        }
        float4 inv = make_float4(0.25f / (sum.x + 1e-8f), 0.25f / (sum.y + 1e-8f),
                                 0.25f / (sum.z + 1e-8f), 0.25f / (sum.w + 1e-8f));
        for (int jj = 0; jj < deg; jj++) {
            int c = __ldg(&g_cols[rp0 + jj]);
            float4 q = ((const float4*)g_qagg)[c];
            float a = __expf(kact.x * q.x - m.x) * inv.x
                    + __expf(kact.y * q.y - m.y) * inv.y
                    + __expf(kact.z * q.z - m.z) * inv.z
                    + __expf(kact.w * q.w - m.w) * inv.w;
            float4 v = *(const float4*)&g_hproj[(size_t)c * DIM + lane * 4];
            acc.x += a * v.x; acc.y += a * v.y; acc.z += a * v.z; acc.w += a * v.w;
        }
    }

    acc.x = leaky_f(acc.x); acc.y = leaky_f(acc.y);
    acc.z = leaky_f(acc.z); acc.w = leaky_f(acc.w);
    *(float4*)&out[(size_t)node * DIM + lane * 4] = acc;
}

// ---------------- launch ----------------
extern "C" void kernel_launch(void* const* d_in, const int* in_sizes, int n_in,
                              void* d_out, int out_size) {
    const float* x  = (const float*)d_in[0];
    const int*   ei = (const int*)d_in[1];
    const float* Wq = (const float*)d_in[2];
    const float* Wk = (const float*)d_in[3];
    const float* Wl = (const float*)d_in[4];
    const float* bl = (const float*)d_in[5];
    float* out = (float*)d_out;

    const int TB = 256;
    const int EDGE_BLOCKS = (N_EDGES + TB - 1) / TB;
    const int NODE_WARP_BLOCKS = (N_NODES * 32 + TB - 1) / TB;

    k_zero_deg<<<(N_NODES + TB - 1) / TB, TB>>>();
    k_hist<<<EDGE_BLOCKS, TB>>>(ei);
    k_scan<<<1, 1024>>>();
    k_scatter<<<EDGE_BLOCKS, TB>>>(ei);
    k_qk<<<NODE_WARP_BLOCKS, TB>>>(x, Wq, Wk);
    k_gemm<<<(N_NODES + 127) / 128, TB>>>(x, Wl, bl);
    k_qagg_csr<<<NODE_WARP_BLOCKS, TB>>>();
    k_fused<<<NODE_WARP_BLOCKS, TB>>>(out);
}